// round 17
// baseline (speedup 1.0000x reference)
#include <cuda_runtime.h>

typedef unsigned long long ull;

#define NPOINTS 32768
#define HW      4096
#define NCODES  8192
#define NSLICE  32
#define KSLICE  (NCODES / NSLICE)   // 256 codes per slice
#define PAIRS   (KSLICE / 2)        // 128 code-pairs per slice
#define T1      64                  // threads per CTA (2 warps)
#define PPT     4                   // points per thread
#define PGROUPS (NPOINTS / (T1 * PPT))  // 128  -> grid = 4096 CTAs

// Scratch (device globals — zero-initialized at module load; no allocation
// allowed in kernel_launch). INVARIANT at every kernel_launch entry:
// g_key all-zero, g_done all-zero, g_ctr zero; the kernel restores all three.
__device__ ull   g_key[NPOINTS];    // ~((monotonic d2 bits << 32) | idx); 0 = empty
__device__ float g_partial[PGROUPS];
__device__ int   g_done[PGROUPS];   // per-point-group slice-completion counter
__device__ int   g_ctr;             // pg-finalizer completion counter

// ---- packed f32x2 helpers (sm_103a); per-lane IEEE rn, same as scalar ----
__device__ __forceinline__ ull fma2(ull a, ull b, ull c) {
    ull d;
    asm("fma.rn.f32x2 %0, %1, %2, %3;" : "=l"(d) : "l"(a), "l"(b), "l"(c));
    return d;
}
__device__ __forceinline__ ull add2(ull a, ull b) {
    ull d;
    asm("add.rn.f32x2 %0, %1, %2;" : "=l"(d) : "l"(a), "l"(b));
    return d;
}
__device__ __forceinline__ ull mul2(ull a, ull b) {
    ull d;
    asm("mul.rn.f32x2 %0, %1, %2;" : "=l"(d) : "l"(a), "l"(b));
    return d;
}
__device__ __forceinline__ ull pack2(float lo, float hi) {
    ull d;
    asm("mov.b64 %0, {%1, %2};" : "=l"(d) : "f"(lo), "f"(hi));
    return d;
}
__device__ __forceinline__ void unpack2(ull v, float& lo, float& hi) {
    asm("mov.b64 {%0, %1}, %2;" : "=f"(lo), "=f"(hi) : "l"(v));
}

// total-order map: float bits -> u32 where smaller float => smaller uint
__device__ __forceinline__ unsigned fmono(float x) {
    unsigned b = __float_as_uint(x);
    return (b & 0x80000000u) ? ~b : (b | 0x80000000u);
}

// Reference fp32 1x1-conv einsum + bias, XLA/cuBLAS association:
//   dot = ascending-k FFMA chain starting from x0*w0; z = dot + b (bias LAST).
__device__ __forceinline__ void compute_z(
    const float* __restrict__ zin, const float* w /*16*/,
    const float* bb /*4*/, int p, float z[4])
{
    int b = p >> 12, hw = p & (HW - 1);
    const float* base = zin + b * (4 * HW) + hw;
    float x0 = base[0], x1 = base[HW], x2 = base[2 * HW], x3 = base[3 * HW];
#pragma unroll
    for (int o = 0; o < 4; o++) {
        float acc = __fmul_rn(x0, w[o * 4 + 0]);
        acc = __fmaf_rn(x1, w[o * 4 + 1], acc);
        acc = __fmaf_rn(x2, w[o * 4 + 2], acc);
        acc = __fmaf_rn(x3, w[o * 4 + 3], acc);
        z[o] = __fadd_rn(acc, bb[o]);
    }
}

// sum of squares, XLA style: elementwise multiply THEN sequential add (no FMA)
__device__ __forceinline__ float sumsq4(float a, float b, float c, float d) {
    float m0 = __fmul_rn(a, a), m1 = __fmul_rn(b, b);
    float m2 = __fmul_rn(c, c), m3 = __fmul_rn(d, d);
    return __fadd_rn(__fadd_rn(__fadd_rn(m0, m1), m2), m3);
}

// d2 pair for pair-record q, given zn (=-2z packed) and szz (packed):
//   acc == -2*dot with reference per-step roundings; d2 = (szz-2dot)+scc
__device__ __forceinline__ ull d2_pair(const ull* q, const ull zn[4], ull szz2) {
    ull acc = mul2(zn[0], q[0]);
    acc = fma2(zn[1], q[1], acc);
    acc = fma2(zn[2], q[2], acc);
    acc = fma2(zn[3], q[3], acc);
    ull t = add2(szz2, acc);
    return add2(t, q[4]);
}

// ============================================================================
// Single fused kernel: per (point-group, code-slice) CTA scans 256 codes for
// 256 points, merging via atomicMax on the INVERTED monotonic key
// (max key' == min (d2, idx); 0 = identity = zero-init; first-occurrence ties).
// The LAST slice-CTA of each point-group (g_done counter) then finalizes its
// 256 points in-place: z recovered bit-exactly as -0.5*zn, keys read from L2,
// gather + straight-through latent + loss partial. The last pg-finalizer
// (g_ctr) does the fixed-tree loss reduction. All scratch restored to zero.
// ============================================================================
__global__ __launch_bounds__(T1) void vq_fused(
    const float* __restrict__ zin,   // [8,4,64,64]
    const float* __restrict__ Wm,    // [4,4]
    const float* __restrict__ bv,    // [4]
    const float* __restrict__ cb,    // [8192,4]
    float* __restrict__ out,
    int loss_idx)
{
    __shared__ float s[PAIRS * 12];
    __shared__ float wq[16], bb[4];
    __shared__ bool  s_lastslice, s_lastpg;
    __shared__ float wsum[T1 / 32];
    const int tid   = threadIdx.x;
    const int pg    = blockIdx.x;   // 0..127
    const int slice = blockIdx.y;   // 0..31
    const int k0    = slice * KSLICE;

    if (tid < 16) wq[tid] = __ldg(Wm + tid);
    if (tid < 4)  bb[tid] = __ldg(bv + tid);

    // Build codebook slice + fp32 |c|^2 (mul-then-add order) in smem
#pragma unroll
    for (int kk = tid; kk < KSLICE; kk += T1) {
        float4 c = ((const float4*)cb)[k0 + kk];
        int pr = kk >> 1, ln = kk & 1;
        float* d = s + pr * 12;
        d[0 + ln] = c.x;
        d[2 + ln] = c.y;
        d[4 + ln] = c.z;
        d[6 + ln] = c.w;
        d[8 + ln] = sumsq4(c.x, c.y, c.z, c.w);
    }
    __syncthreads();

    ull zn[PPT][4];   // -2*z_d duplicated in both halves (exact scaling)
    ull szz2[PPT];    // ||z||^2 duplicated
#pragma unroll
    for (int j = 0; j < PPT; j++) {
        int p = pg * (T1 * PPT) + j * T1 + tid;  // coalesced over tid
        float z[4];
        compute_z(zin, wq, bb, p, z);
        float szz = sumsq4(z[0], z[1], z[2], z[3]);
        szz2[j] = pack2(szz, szz);
#pragma unroll
        for (int o = 0; o < 4; o++) {
            float m = -2.0f * z[o];   // exact (power-of-two scale + negate)
            zn[j][o] = pack2(m, m);
        }
    }

    float best[PPT];
    int   bpr[PPT];
#pragma unroll
    for (int j = 0; j < PPT; j++) { best[j] = 3.4e38f; bpr[j] = 0; }

#pragma unroll 8
    for (int pr = 0; pr < PAIRS; ++pr) {
        const ull* q = (const ull*)(s + pr * 12);  // 48B stride, 16B aligned
        ull m0 = q[0], m1 = q[1], m2 = q[2], m3 = q[3], cc = q[4];
#pragma unroll
        for (int j = 0; j < PPT; j++) {
            ull acc = mul2(zn[j][0], m0);
            acc = fma2(zn[j][1], m1, acc);
            acc = fma2(zn[j][2], m2, acc);
            acc = fma2(zn[j][3], m3, acc);
            ull t  = add2(szz2[j], acc);   // rn(szz - 2*dot)
            ull d2 = add2(t, cc);          // + ||c||^2
            float s0, s1;
            unpack2(d2, s0, s1);
            // lane-reduce then pair-track: 4 ALU ops total
            float pm  = fminf(s0, s1);
            bool  imp = (pm < best[j]);        // strict: earliest pair on ties
            best[j] = fminf(best[j], pm);
            bpr[j]  = imp ? pr : bpr[j];
        }
    }

    // Recover winning lane, publish via atomicMax on inverted key
#pragma unroll
    for (int j = 0; j < PPT; j++) {
        int p = pg * (T1 * PPT) + j * T1 + tid;
        const ull* q = (const ull*)(s + bpr[j] * 12);
        float s0, s1;
        unpack2(d2_pair(q, zn[j], szz2[j]), s0, s1);
        // even lane preferred on equality (lower k = first occurrence)
        int lane = (__float_as_int(s0) == __float_as_int(best[j])) ? 0 : 1;
        unsigned idx = (unsigned)(k0 + 2 * bpr[j] + lane);
        ull key = ~(((ull)fmono(best[j]) << 32) | idx);
        atomicMax(&g_key[p], key);   // RED.MAX.U64, spread addresses
    }

    // ---- slice-completion handshake (threadfence-reduction pattern) ----
    __threadfence();                 // make this thread's REDs visible
    __syncthreads();                 // all threads have fenced
    if (tid == 0)
        s_lastslice = (atomicAdd(&g_done[pg], 1) == NSLICE - 1);
    __syncthreads();
    if (!s_lastslice) return;

    // ================= FINALIZE (this CTA is last for pg) =================
    if (tid == 0) g_done[pg] = 0;    // restore invariant for next replay

    float acc = 0.f;
#pragma unroll
    for (int j = 0; j < PPT; j++) {
        int p = pg * (T1 * PPT) + j * T1 + tid;
        ull keyp = __ldcg(&g_key[p]);       // L2-coherent (all peers fenced)
        __stcg(&g_key[p], 0ull);            // restore invariant
        int idx = (int)(unsigned)((~keyp) & 0xFFFFFFFFull);

        // z recovered bit-exactly: z = -0.5 * (-2z)
        float z0, z1, z2, z3, dummy;
        unpack2(zn[j][0], z0, dummy); z0 = -0.5f * z0;
        unpack2(zn[j][1], z1, dummy); z1 = -0.5f * z1;
        unpack2(zn[j][2], z2, dummy); z2 = -0.5f * z2;
        unpack2(zn[j][3], z3, dummy); z3 = -0.5f * z3;

        float4 c = ((const float4*)cb)[idx];
        const int b  = p >> 12;
        const int hw = p & (HW - 1);
        float* ob = out + b * (4 * HW) + hw;
        // straight-through: z + (zq - z), two roundings, as in the reference
        float r0 = __fadd_rn(c.x, -z0);
        float r1 = __fadd_rn(c.y, -z1);
        float r2 = __fadd_rn(c.z, -z2);
        float r3 = __fadd_rn(c.w, -z3);
        ob[0]      = __fadd_rn(z0, r0);
        ob[HW]     = __fadd_rn(z1, r1);
        ob[2 * HW] = __fadd_rn(z2, r2);
        ob[3 * HW] = __fadd_rn(z3, r3);

        acc = __fadd_rn(acc, sumsq4(r0, r1, r2, r3));
    }

    // loss partial for this pg: warp reduce (fixed order), 2-warp combine
#pragma unroll
    for (int o = 16; o > 0; o >>= 1)
        acc += __shfl_down_sync(0xffffffffu, acc, o);
    if ((tid & 31) == 0) wsum[tid >> 5] = acc;
    __syncthreads();
    if (tid == 0) {
        __stcg(&g_partial[pg], wsum[0] + wsum[1]);
        __threadfence();
        s_lastpg = (atomicAdd(&g_ctr, 1) == PGROUPS - 1);
    }
    __syncthreads();
    if (!s_lastpg) return;

    // ============== final loss reduction (last pg-finalizer) ==============
    {
        __shared__ float red[T1];
        // fixed order: red[t] = partial[t] + partial[t+64]
        red[tid] = __ldcg(&g_partial[tid]) + __ldcg(&g_partial[tid + T1]);
        __syncthreads();
#pragma unroll
        for (int st = T1 / 2; st > 0; st >>= 1) {
            if (tid < st) red[tid] += red[tid + st];
            __syncthreads();
        }
        if (tid == 0) {
            out[loss_idx] = red[0] * (1.25f / (float)(NPOINTS * 4));
            g_ctr = 0;   // restore invariant for next replay
        }
    }
}

extern "C" void kernel_launch(void* const* d_in, const int* in_sizes, int n_in,
                              void* d_out, int out_size)
{
    const float* zin = (const float*)d_in[0];  // z_e_in [8,4,64,64]
    const float* Wm  = (const float*)d_in[1];  // pq_w [4,4]
    const float* bv  = (const float*)d_in[2];  // pq_b [4]
    const float* cb  = (const float*)d_in[3];  // codebook [8192,4]
    float* out = (float*)d_out;

    dim3 g1(PGROUPS, NSLICE);
    vq_fused<<<g1, T1>>>(zin, Wm, bv, cb, out, out_size - 1);
}